// round 10
// baseline (speedup 1.0000x reference)
#include <cuda_runtime.h>
#include <cstdint>
#include <cstddef>

#define F 128
#define MAXN 100000
#define MAXE 1600000

typedef unsigned long long ull;

// Scratch (allocation-free rule: __device__ globals). 16B-aligned for float4.
__device__ __align__(16) float  g_h[MAXN * F];    // post-GEMM features
__device__ __align__(16) float  g_y[MAXN * F];    // layer-1 activated output
__device__ float g_dinv[MAXN];                    // deg^{-1/2}
__device__ __align__(16) float2 g_Wt2[F * F];     // W^T with duplicated entries {w,w}
__device__ int   g_src[MAXE];
__device__ int   g_dst[MAXE];
__device__ int   g_degi[MAXN];                    // in-degree histogram
__device__ int   g_off[MAXN + 1];                 // CSR row offsets (by dst)
__device__ int   g_cursor[MAXN];                  // placement cursors
__device__ int   g_csr_src[MAXE];                 // src ids grouped by dst
__device__ int   g_is64;

#define FMA2(d, a, b) asm("fma.rn.f32x2 %0, %1, %2, %3;" : "=l"(d) : "l"(a), "l"(b), "l"(d))

static __device__ __forceinline__ float2 upk(ull v) {
    float2 r;
    asm("mov.b64 {%0, %1}, %2;" : "=f"(r.x), "=f"(r.y) : "l"(v));
    return r;
}

// ---------------- edge_index dtype detection + decode ----------------
__global__ void k_detect(const int* __restrict__ w, int E) {
    if (blockIdx.x == 0 && threadIdx.x == 0) {
        int all0 = 1;
        int cnt = E < 256 ? E : 256;
        for (int i = 0; i < cnt; i++)
            if (w[2 * i + 1] != 0) { all0 = 0; break; }
        g_is64 = all0;
    }
}

__global__ void k_decode(const int* __restrict__ w, int E) {
    int e = blockIdx.x * blockDim.x + threadIdx.x;
    if (e < E) {
        if (g_is64) {
            g_src[e] = w[2 * e];
            g_dst[e] = w[2 * (E + e)];
        } else {
            g_src[e] = w[e];
            g_dst[e] = w[E + e];
        }
    }
}

// ---------------- degree histogram (re-zeroed every replay) ----------------
__global__ void k_zero_deg(int n) {
    int i = blockIdx.x * blockDim.x + threadIdx.x;
    if (i < n) g_degi[i] = 0;
}

__global__ void k_count_deg(int E, int n) {
    int e = blockIdx.x * blockDim.x + threadIdx.x;
    if (e < E) {
        int d = g_dst[e];
        if ((unsigned)d < (unsigned)n) atomicAdd(&g_degi[d], 1);
    }
}

__global__ void k_rsqrt(int n) {
    int i = blockIdx.x * blockDim.x + threadIdx.x;
    if (i < n) g_dinv[i] = rsqrtf((float)g_degi[i] + 1.0f);
}

// ---------------- exclusive scan over degrees -> CSR offsets ----------------
__global__ void __launch_bounds__(1024) k_scan(int n) {
    __shared__ int warp_base[32];
    __shared__ int carry;
    const int tid = threadIdx.x;
    const int lane = tid & 31, wid = tid >> 5;
    if (tid == 0) carry = 0;
    __syncthreads();

    for (int start = 0; start < n; start += 1024) {
        int i = start + tid;
        int v = (i < n) ? g_degi[i] : 0;
        int x = v;
#pragma unroll
        for (int o = 1; o < 32; o <<= 1) {
            int y = __shfl_up_sync(0xffffffffu, x, o);
            if (lane >= o) x += y;
        }
        if (lane == 31) warp_base[wid] = x;
        __syncthreads();
        if (tid < 32) {
            int w = warp_base[tid];
            int y = w;
#pragma unroll
            for (int o = 1; o < 32; o <<= 1) {
                int z = __shfl_up_sync(0xffffffffu, y, o);
                if (tid >= o) y += z;
            }
            warp_base[tid] = y - w;   // exclusive base per warp
        }
        __syncthreads();
        int excl = carry + warp_base[wid] + (x - v);
        if (i < n) { g_off[i] = excl; g_cursor[i] = excl; }
        __syncthreads();
        if (tid == 1023) carry += warp_base[31] + x;
        __syncthreads();
    }
    if (tid == 0) g_off[n] = carry;
}

// ---------------- edge placement: group src by dst ----------------
__global__ void k_place(int E, int n) {
    int e = blockIdx.x * blockDim.x + threadIdx.x;
    if (e < E) {
        int d = g_dst[e];
        int s = g_src[e];
        if ((unsigned)d < (unsigned)n && (unsigned)s < (unsigned)n) {
            int pos = atomicAdd(&g_cursor[d], 1);
            g_csr_src[pos] = s;
        }
    }
}

// ---------------- W transpose + duplicate: g_Wt2[k*F+j] = {W[j][k], W[j][k]} --
__global__ void k_transdup(const float* __restrict__ W) {
    int i = blockIdx.x * blockDim.x + threadIdx.x;  // 16384 threads
    int j = i >> 7, k = i & 127;
    float w = W[i];
    g_Wt2[k * F + j] = make_float2(w, w);
}

// ---------------- GEMM: h = in @ W^T (packed f32x2) ----------------
// Block: 128 threads, tile 64 rows x 128 cols.
// warp w -> rows 16w..16w+15 ; lane l -> cols 4l..4l+3.
// Accumulators are f32x2 row-pairs; W loaded pre-duplicated.
__global__ void __launch_bounds__(128) k_gemm2(const float* __restrict__ in,
                                               float* __restrict__ h,
                                               int n) {
    __shared__ __align__(16) float xs[F * 68];   // xs[k*68 + r], r = 0..63
    const int tid = threadIdx.x;
    const int node0 = blockIdx.x * 64;

    for (int e = tid; e < 64 * F; e += 128) {
        int r = e >> 7, k = e & 127;
        int nn = node0 + r;
        xs[k * 68 + r] = (nn < n) ? in[(size_t)nn * F + k] : 0.0f;
    }
    __syncthreads();

    const int w    = tid >> 5;
    const int lane = tid & 31;
    const int r0   = w * 16;
    const int j    = lane * 4;

    ull acc[8][4];
#pragma unroll
    for (int p = 0; p < 8; p++)
#pragma unroll
        for (int c = 0; c < 4; c++) acc[p][c] = 0ULL;

#pragma unroll 4
    for (int k = 0; k < F; k++) {
        // 16 row values = 8 packed pairs (broadcast LDS.128)
        const ulonglong2* xp = (const ulonglong2*)&xs[k * 68 + r0];
        ulonglong2 q0 = xp[0], q1 = xp[1], q2 = xp[2], q3 = xp[3];
        ull rp[8] = {q0.x, q0.y, q1.x, q1.y, q2.x, q2.y, q3.x, q3.y};
        // 4 duplicated weights = 2 LDG.128 (L1-resident)
        const ulonglong2* wp = (const ulonglong2*)&g_Wt2[k * F + j];
        ulonglong2 wa = wp[0], wb = wp[1];
        ull wd[4] = {wa.x, wa.y, wb.x, wb.y};
#pragma unroll
        for (int p = 0; p < 8; p++) {
#pragma unroll
            for (int c = 0; c < 4; c++) FMA2(acc[p][c], rp[p], wd[c]);
        }
    }

    // epilogue: unpack row-pairs, store float4 per row
#pragma unroll
    for (int p = 0; p < 8; p++) {
        float2 c0 = upk(acc[p][0]);
        float2 c1 = upk(acc[p][1]);
        float2 c2 = upk(acc[p][2]);
        float2 c3 = upk(acc[p][3]);
        int rlo = node0 + r0 + 2 * p;
        int rhi = rlo + 1;
        if (rlo < n) {
            float4 v = make_float4(c0.x, c1.x, c2.x, c3.x);
            *(float4*)&h[(size_t)rlo * F + j] = v;
        }
        if (rhi < n) {
            float4 v = make_float4(c0.y, c1.y, c2.y, c3.y);
            *(float4*)&h[(size_t)rhi * F + j] = v;
        }
    }
}

// ---------------- fused aggregation + self-loop + bias + leaky-relu ---------
// One warp per dst node; lane handles 4 features (float4). No atomics.
__global__ void __launch_bounds__(256) k_agg(const float* __restrict__ h,
                                             const float* __restrict__ b,
                                             float* __restrict__ o,
                                             int n) {
    const int lane = threadIdx.x & 31;
    const int d = (blockIdx.x * blockDim.x + threadIdx.x) >> 5;
    if (d >= n) return;

    const int beg = g_off[d];
    const int end = g_off[d + 1];
    const float did = g_dinv[d];

    float4 hv = ((const float4*)(h + (size_t)d * F))[lane];
    float4 bb = ((const float4*)b)[lane];
    const float sw = did * did;
    float4 acc;
    acc.x = fmaf(hv.x, sw, bb.x);
    acc.y = fmaf(hv.y, sw, bb.y);
    acc.z = fmaf(hv.z, sw, bb.z);
    acc.w = fmaf(hv.w, sw, bb.w);

    int j = beg;
    for (; j + 1 < end; j += 2) {
        int s0 = g_csr_src[j];
        int s1 = g_csr_src[j + 1];
        float n0 = g_dinv[s0] * did;
        float n1 = g_dinv[s1] * did;
        float4 v0 = ((const float4*)(h + (size_t)s0 * F))[lane];
        float4 v1 = ((const float4*)(h + (size_t)s1 * F))[lane];
        acc.x = fmaf(v0.x, n0, acc.x); acc.y = fmaf(v0.y, n0, acc.y);
        acc.z = fmaf(v0.z, n0, acc.z); acc.w = fmaf(v0.w, n0, acc.w);
        acc.x = fmaf(v1.x, n1, acc.x); acc.y = fmaf(v1.y, n1, acc.y);
        acc.z = fmaf(v1.z, n1, acc.z); acc.w = fmaf(v1.w, n1, acc.w);
    }
    if (j < end) {
        int s0 = g_csr_src[j];
        float n0 = g_dinv[s0] * did;
        float4 v0 = ((const float4*)(h + (size_t)s0 * F))[lane];
        acc.x = fmaf(v0.x, n0, acc.x); acc.y = fmaf(v0.y, n0, acc.y);
        acc.z = fmaf(v0.z, n0, acc.z); acc.w = fmaf(v0.w, n0, acc.w);
    }

    acc.x = acc.x > 0.0f ? acc.x : 0.01f * acc.x;
    acc.y = acc.y > 0.0f ? acc.y : 0.01f * acc.y;
    acc.z = acc.z > 0.0f ? acc.z : 0.01f * acc.z;
    acc.w = acc.w > 0.0f ? acc.w : 0.01f * acc.w;
    ((float4*)(o + (size_t)d * F))[lane] = acc;
}

extern "C" void kernel_launch(void* const* d_in, const int* in_sizes, int n_in,
                              void* d_out, int out_size) {
    // Assign inputs by element count (robust to ordering).
    const float* x = nullptr; const int* ei = nullptr;
    const float* W1 = nullptr; const float* b1 = nullptr;
    const float* W2 = nullptr; const float* b2 = nullptr;
    int x_elems = 0, ei_elems = 0;

    for (int i = 0; i < n_in; i++) {
        int s = in_sizes[i];
        if (s == F * F)      { if (!W1) W1 = (const float*)d_in[i]; else W2 = (const float*)d_in[i]; }
        else if (s == F)     { if (!b1) b1 = (const float*)d_in[i]; else b2 = (const float*)d_in[i]; }
        else if (s > 4 * F * F) {
            if (!x) { x = (const float*)d_in[i]; x_elems = s; }
            else    { ei = (const int*)d_in[i]; ei_elems = s; }
        }
    }
    if (x && ei && x_elems < ei_elems) {
        const float* t = x; x = (const float*)ei; ei = (const int*)t;
        int te = x_elems; x_elems = ei_elems; ei_elems = te;
    }

    const int N = x_elems / F;
    const int E = ei_elems / 2;
    float* out = (float*)d_out;

    float *h, *y;
    cudaGetSymbolAddress((void**)&h, g_h);
    cudaGetSymbolAddress((void**)&y, g_y);

    const int TB = 256;
    const int nblk = (N + TB - 1) / TB;
    const int eblk = (E + TB - 1) / TB;
    const int gblk = (N + 63) / 64;
    const int ablk = (N * 32 + TB - 1) / TB;   // warp per node

    // edges -> canonical int32, degrees, CSR
    k_detect<<<1, 32>>>(ei, E);
    k_decode<<<eblk, TB>>>(ei, E);
    k_zero_deg<<<nblk, TB>>>(N);
    k_count_deg<<<eblk, TB>>>(E, N);
    k_rsqrt<<<nblk, TB>>>(N);
    k_scan<<<1, 1024>>>(N);
    k_place<<<eblk, TB>>>(E, N);

    // ---- layer 1 ----
    k_transdup<<<64, 256>>>(W1);
    k_gemm2<<<gblk, 128>>>(x, h, N);
    k_agg<<<ablk, TB>>>(h, b1, y, N);

    // ---- layer 2 ----
    k_transdup<<<64, 256>>>(W2);
    k_gemm2<<<gblk, 128>>>(y, h, N);
    k_agg<<<ablk, TB>>>(h, b2, out, N);
}

// round 11
// speedup vs baseline: 1.0901x; 1.0901x over previous
#include <cuda_runtime.h>
#include <cstdint>
#include <cstddef>

#define F 128
#define MAXN 100000
#define MAXE 1600000

// Scratch (allocation-free rule: __device__ globals). 16B-aligned for float4.
__device__ __align__(16) float g_h[MAXN * F];     // post-GEMM features
__device__ __align__(16) float g_y[MAXN * F];     // layer-1 activated output
__device__ float g_dinv[MAXN];                    // deg^{-1/2}
__device__ int   g_src[MAXE];
__device__ int   g_dst[MAXE];
__device__ int   g_degi[MAXN];                    // in-degree histogram
__device__ int   g_beg[MAXN];                     // CSR range start (atomic alloc)
__device__ int   g_cursor[MAXN];                  // placement cursors
__device__ int   g_csr_src[MAXE];                 // src ids grouped by dst
__device__ int   g_is64;
__device__ int   g_total;

// ---------------- edge_index dtype detection ----------------
__global__ void k_detect(const int* __restrict__ w, int E) {
    if (blockIdx.x == 0 && threadIdx.x == 0) {
        int all0 = 1;
        int cnt = E < 256 ? E : 256;
        for (int i = 0; i < cnt; i++)
            if (w[2 * i + 1] != 0) { all0 = 0; break; }
        g_is64 = all0;
    }
}

// ---------------- zero histogram + allocator counter ----------------
__global__ void k_zero(int n) {
    int i = blockIdx.x * blockDim.x + threadIdx.x;
    if (i < n) g_degi[i] = 0;
    if (i == 0) g_total = 0;
}

// ---------------- decode + degree count in one pass ----------------
__global__ void k_decode_count(const int* __restrict__ w, int E, int n) {
    int e = blockIdx.x * blockDim.x + threadIdx.x;
    if (e < E) {
        int s, d;
        if (g_is64) {
            s = w[2 * e];
            d = w[2 * (E + e)];
        } else {
            s = w[e];
            d = w[E + e];
        }
        g_src[e] = s;
        g_dst[e] = d;
        if ((unsigned)d < (unsigned)n) atomicAdd(&g_degi[d], 1);
    }
}

// ---------------- range allocation (replaces scan) + rsqrt ----------------
__global__ void k_alloc(int n) {
    int i = blockIdx.x * blockDim.x + threadIdx.x;
    if (i < n) {
        int deg = g_degi[i];
        int beg = atomicAdd(&g_total, deg);
        g_beg[i] = beg;
        g_cursor[i] = beg;
        g_dinv[i] = rsqrtf((float)deg + 1.0f);
    }
}

// ---------------- edge placement: group src by dst ----------------
__global__ void k_place(int E, int n) {
    int e = blockIdx.x * blockDim.x + threadIdx.x;
    if (e < E) {
        int d = g_dst[e];
        int s = g_src[e];
        if ((unsigned)d < (unsigned)n && (unsigned)s < (unsigned)n) {
            int pos = atomicAdd(&g_cursor[d], 1);
            g_csr_src[pos] = s;
        }
    }
}

// ---------------- GEMM: h = in @ W^T (W read directly, L1-resident) --------
// Block: 128 threads (thread = output column j), 32 node rows per block.
__global__ void __launch_bounds__(128) k_gemm(const float* __restrict__ in,
                                              const float* __restrict__ W,
                                              float* __restrict__ h,
                                              int n) {
    __shared__ float xs[F * 36];   // xs[k*36 + r], pad avoids bank conflicts
    const int tid = threadIdx.x;
    const int node0 = blockIdx.x * 32;

#pragma unroll
    for (int r = 0; r < 32; r++) {
        int nn = node0 + r;
        xs[tid * 36 + r] = (nn < n) ? in[(size_t)nn * F + tid] : 0.0f;
    }
    __syncthreads();

    float acc[32];
#pragma unroll
    for (int r = 0; r < 32; r++) acc[r] = 0.0f;

    const int j = tid;
    const float* Wrow = W + (size_t)j * F;   // thread's own contiguous row
#pragma unroll 2
    for (int k4 = 0; k4 < F; k4 += 4) {
        float4 wv = *(const float4*)&Wrow[k4];
        float wk[4] = {wv.x, wv.y, wv.z, wv.w};
#pragma unroll
        for (int kk = 0; kk < 4; kk++) {
            const float* xr = &xs[(k4 + kk) * 36];
            float w = wk[kk];
#pragma unroll
            for (int r = 0; r < 32; r++) acc[r] = fmaf(xr[r], w, acc[r]);
        }
    }

#pragma unroll
    for (int r = 0; r < 32; r++) {
        int nn = node0 + r;
        if (nn < n) h[(size_t)nn * F + j] = acc[r];
    }
}

// ---------------- fused aggregation + self-loop + bias + leaky-relu ---------
// One warp per dst node; lane handles 4 features (float4). No atomics.
__global__ void __launch_bounds__(256) k_agg(const float* __restrict__ h,
                                             const float* __restrict__ b,
                                             float* __restrict__ o,
                                             int n) {
    const int lane = threadIdx.x & 31;
    const int d = (blockIdx.x * blockDim.x + threadIdx.x) >> 5;
    if (d >= n) return;

    const int beg = g_beg[d];
    const int end = beg + g_degi[d];
    const float did = g_dinv[d];

    float4 hv = ((const float4*)(h + (size_t)d * F))[lane];
    float4 bb = ((const float4*)b)[lane];
    const float sw = did * did;
    float4 acc;
    acc.x = fmaf(hv.x, sw, bb.x);
    acc.y = fmaf(hv.y, sw, bb.y);
    acc.z = fmaf(hv.z, sw, bb.z);
    acc.w = fmaf(hv.w, sw, bb.w);

    int j = beg;
    for (; j + 3 < end; j += 4) {            // 4-wide for MLP
        int s0 = g_csr_src[j];
        int s1 = g_csr_src[j + 1];
        int s2 = g_csr_src[j + 2];
        int s3 = g_csr_src[j + 3];
        float n0 = g_dinv[s0] * did;
        float n1 = g_dinv[s1] * did;
        float n2 = g_dinv[s2] * did;
        float n3 = g_dinv[s3] * did;
        float4 v0 = ((const float4*)(h + (size_t)s0 * F))[lane];
        float4 v1 = ((const float4*)(h + (size_t)s1 * F))[lane];
        float4 v2 = ((const float4*)(h + (size_t)s2 * F))[lane];
        float4 v3 = ((const float4*)(h + (size_t)s3 * F))[lane];
        acc.x = fmaf(v0.x, n0, acc.x); acc.y = fmaf(v0.y, n0, acc.y);
        acc.z = fmaf(v0.z, n0, acc.z); acc.w = fmaf(v0.w, n0, acc.w);
        acc.x = fmaf(v1.x, n1, acc.x); acc.y = fmaf(v1.y, n1, acc.y);
        acc.z = fmaf(v1.z, n1, acc.z); acc.w = fmaf(v1.w, n1, acc.w);
        acc.x = fmaf(v2.x, n2, acc.x); acc.y = fmaf(v2.y, n2, acc.y);
        acc.z = fmaf(v2.z, n2, acc.z); acc.w = fmaf(v2.w, n2, acc.w);
        acc.x = fmaf(v3.x, n3, acc.x); acc.y = fmaf(v3.y, n3, acc.y);
        acc.z = fmaf(v3.z, n3, acc.z); acc.w = fmaf(v3.w, n3, acc.w);
    }
    for (; j < end; j++) {
        int s0 = g_csr_src[j];
        float n0 = g_dinv[s0] * did;
        float4 v0 = ((const float4*)(h + (size_t)s0 * F))[lane];
        acc.x = fmaf(v0.x, n0, acc.x); acc.y = fmaf(v0.y, n0, acc.y);
        acc.z = fmaf(v0.z, n0, acc.z); acc.w = fmaf(v0.w, n0, acc.w);
    }

    acc.x = acc.x > 0.0f ? acc.x : 0.01f * acc.x;
    acc.y = acc.y > 0.0f ? acc.y : 0.01f * acc.y;
    acc.z = acc.z > 0.0f ? acc.z : 0.01f * acc.z;
    acc.w = acc.w > 0.0f ? acc.w : 0.01f * acc.w;
    ((float4*)(o + (size_t)d * F))[lane] = acc;
}

extern "C" void kernel_launch(void* const* d_in, const int* in_sizes, int n_in,
                              void* d_out, int out_size) {
    // Assign inputs by element count (robust to ordering).
    const float* x = nullptr; const int* ei = nullptr;
    const float* W1 = nullptr; const float* b1 = nullptr;
    const float* W2 = nullptr; const float* b2 = nullptr;
    int x_elems = 0, ei_elems = 0;

    for (int i = 0; i < n_in; i++) {
        int s = in_sizes[i];
        if (s == F * F)      { if (!W1) W1 = (const float*)d_in[i]; else W2 = (const float*)d_in[i]; }
        else if (s == F)     { if (!b1) b1 = (const float*)d_in[i]; else b2 = (const float*)d_in[i]; }
        else if (s > 4 * F * F) {
            if (!x) { x = (const float*)d_in[i]; x_elems = s; }
            else    { ei = (const int*)d_in[i]; ei_elems = s; }
        }
    }
    if (x && ei && x_elems < ei_elems) {
        const float* t = x; x = (const float*)ei; ei = (const int*)t;
        int te = x_elems; x_elems = ei_elems; ei_elems = te;
    }

    const int N = x_elems / F;
    const int E = ei_elems / 2;
    float* out = (float*)d_out;

    float *h, *y;
    cudaGetSymbolAddress((void**)&h, g_h);
    cudaGetSymbolAddress((void**)&y, g_y);

    const int TB = 256;
    const int nblk = (N + TB - 1) / TB;
    const int eblk = (E + TB - 1) / TB;
    const int gblk = (N + 31) / 32;
    const int ablk = (N * 32 + TB - 1) / TB;   // warp per node

    // CSR build: detect(0) zero(1) decode+count(2) alloc(3) place(4)
    k_detect<<<1, 32>>>(ei, E);
    k_zero<<<nblk, TB>>>(N);
    k_decode_count<<<eblk, TB>>>(ei, E, N);
    k_alloc<<<nblk, TB>>>(N);
    k_place<<<eblk, TB>>>(E, N);

    // ---- layer 1 ----  (gemm1 = launch #5 -> ncu window)
    k_gemm<<<gblk, 128>>>(x, W1, h, N);
    k_agg<<<ablk, TB>>>(h, b1, y, N);

    // ---- layer 2 ----
    k_gemm<<<gblk, 128>>>(y, W2, h, N);
    k_agg<<<ablk, TB>>>(h, b2, out, N);
}

// round 13
// speedup vs baseline: 1.0980x; 1.0073x over previous
#include <cuda_runtime.h>
#include <cuda_fp16.h>
#include <cstdint>
#include <cstddef>

#define F 128
#define MAXN 100000
#define MAXE 1600000

// Scratch (allocation-free rule: __device__ globals). 16B-aligned for float4.
__device__ __align__(16) float  g_h[MAXN * F];    // post-GEMM features (fp32)
__device__ __align__(16) __half g_h2[MAXN * F];   // fp16 mirror for gathers
__device__ __align__(16) float  g_y[MAXN * F];    // layer-1 activated output
__device__ float g_dinv[MAXN];                    // deg^{-1/2}
__device__ int   g_src[MAXE];
__device__ int   g_dst[MAXE];
__device__ int   g_degi[MAXN];                    // in-degree histogram
__device__ int   g_beg[MAXN];                     // CSR range start (atomic alloc)
__device__ int   g_cursor[MAXN];                  // placement cursors
__device__ int   g_csr_src[MAXE];                 // src ids grouped by dst
__device__ int   g_is64;
__device__ int   g_total;

// ---------------- edge_index dtype detection ----------------
__global__ void k_detect(const int* __restrict__ w, int E) {
    if (blockIdx.x == 0 && threadIdx.x == 0) {
        int all0 = 1;
        int cnt = E < 256 ? E : 256;
        for (int i = 0; i < cnt; i++)
            if (w[2 * i + 1] != 0) { all0 = 0; break; }
        g_is64 = all0;
    }
}

// ---------------- zero histogram + allocator counter ----------------
__global__ void k_zero(int n) {
    int i = blockIdx.x * blockDim.x + threadIdx.x;
    if (i < n) g_degi[i] = 0;
    if (i == 0) g_total = 0;
}

// ---------------- decode + degree count in one pass ----------------
__global__ void k_decode_count(const int* __restrict__ w, int E, int n) {
    int e = blockIdx.x * blockDim.x + threadIdx.x;
    if (e < E) {
        int s, d;
        if (g_is64) {
            s = w[2 * e];
            d = w[2 * (E + e)];
        } else {
            s = w[e];
            d = w[E + e];
        }
        g_src[e] = s;
        g_dst[e] = d;
        if ((unsigned)d < (unsigned)n) atomicAdd(&g_degi[d], 1);
    }
}

// ---------------- range allocation (replaces scan) + rsqrt ----------------
__global__ void k_alloc(int n) {
    int i = blockIdx.x * blockDim.x + threadIdx.x;
    if (i < n) {
        int deg = g_degi[i];
        int beg = atomicAdd(&g_total, deg);
        g_beg[i] = beg;
        g_cursor[i] = beg;
        g_dinv[i] = rsqrtf((float)deg + 1.0f);
    }
}

// ---------------- edge placement: group src by dst ----------------
__global__ void k_place(int E, int n) {
    int e = blockIdx.x * blockDim.x + threadIdx.x;
    if (e < E) {
        int d = g_dst[e];
        int s = g_src[e];
        if ((unsigned)d < (unsigned)n && (unsigned)s < (unsigned)n) {
            int pos = atomicAdd(&g_cursor[d], 1);
            g_csr_src[pos] = s;
        }
    }
}

// ---------------- GEMM: h = in @ W^T ; also emit fp16 mirror ----------------
// Block: 128 threads (thread = output column j), 32 node rows per block.
__global__ void __launch_bounds__(128) k_gemm(const float* __restrict__ in,
                                              const float* __restrict__ W,
                                              float* __restrict__ h,
                                              __half* __restrict__ h2,
                                              int n) {
    __shared__ float xs[F * 36];   // xs[k*36 + r], pad avoids bank conflicts
    const int tid = threadIdx.x;
    const int node0 = blockIdx.x * 32;

#pragma unroll
    for (int r = 0; r < 32; r++) {
        int nn = node0 + r;
        xs[tid * 36 + r] = (nn < n) ? in[(size_t)nn * F + tid] : 0.0f;
    }
    __syncthreads();

    float acc[32];
#pragma unroll
    for (int r = 0; r < 32; r++) acc[r] = 0.0f;

    const int j = tid;
    const float* Wrow = W + (size_t)j * F;   // thread's own contiguous row
#pragma unroll 2
    for (int k4 = 0; k4 < F; k4 += 4) {
        float4 wv = *(const float4*)&Wrow[k4];
        float wk[4] = {wv.x, wv.y, wv.z, wv.w};
#pragma unroll
        for (int kk = 0; kk < 4; kk++) {
            const float* xr = &xs[(k4 + kk) * 36];
            float w = wk[kk];
#pragma unroll
            for (int r = 0; r < 32; r++) acc[r] = fmaf(xr[r], w, acc[r]);
        }
    }

#pragma unroll
    for (int r = 0; r < 32; r++) {
        int nn = node0 + r;
        if (nn < n) {
            h[(size_t)nn * F + j] = acc[r];
            h2[(size_t)nn * F + j] = __float2half_rn(acc[r]);
        }
    }
}

// ---------------- fused aggregation + self-loop + bias + leaky-relu ---------
// One warp per dst node; lane handles 4 features. Neighbors gathered in fp16
// (half the LTS traffic); self-loop term and bias in fp32.
__global__ void __launch_bounds__(256) k_agg(const float* __restrict__ h,
                                             const __half* __restrict__ h2,
                                             const float* __restrict__ b,
                                             float* __restrict__ o,
                                             int n) {
    const int lane = threadIdx.x & 31;
    const int d = (blockIdx.x * blockDim.x + threadIdx.x) >> 5;
    if (d >= n) return;

    const int beg = g_beg[d];
    const int end = beg + g_degi[d];
    const float did = g_dinv[d];

    float4 hv = ((const float4*)(h + (size_t)d * F))[lane];
    float4 bb = ((const float4*)b)[lane];
    const float sw = did * did;
    float4 acc;
    acc.x = fmaf(hv.x, sw, bb.x);
    acc.y = fmaf(hv.y, sw, bb.y);
    acc.z = fmaf(hv.z, sw, bb.z);
    acc.w = fmaf(hv.w, sw, bb.w);

    int j = beg;
    for (; j + 3 < end; j += 4) {            // 4-wide for MLP
        int s0 = g_csr_src[j];
        int s1 = g_csr_src[j + 1];
        int s2 = g_csr_src[j + 2];
        int s3 = g_csr_src[j + 3];
        float n0 = g_dinv[s0] * did;
        float n1 = g_dinv[s1] * did;
        float n2 = g_dinv[s2] * did;
        float n3 = g_dinv[s3] * did;
        uint2 u0 = ((const uint2*)(h2 + (size_t)s0 * F))[lane];
        uint2 u1 = ((const uint2*)(h2 + (size_t)s1 * F))[lane];
        uint2 u2 = ((const uint2*)(h2 + (size_t)s2 * F))[lane];
        uint2 u3 = ((const uint2*)(h2 + (size_t)s3 * F))[lane];
        float2 a0 = __half22float2(*(const __half2*)&u0.x);
        float2 b0 = __half22float2(*(const __half2*)&u0.y);
        float2 a1 = __half22float2(*(const __half2*)&u1.x);
        float2 b1_ = __half22float2(*(const __half2*)&u1.y);
        float2 a2 = __half22float2(*(const __half2*)&u2.x);
        float2 b2_ = __half22float2(*(const __half2*)&u2.y);
        float2 a3 = __half22float2(*(const __half2*)&u3.x);
        float2 b3_ = __half22float2(*(const __half2*)&u3.y);
        acc.x = fmaf(a0.x, n0, acc.x); acc.y = fmaf(a0.y, n0, acc.y);
        acc.z = fmaf(b0.x, n0, acc.z); acc.w = fmaf(b0.y, n0, acc.w);
        acc.x = fmaf(a1.x, n1, acc.x); acc.y = fmaf(a1.y, n1, acc.y);
        acc.z = fmaf(b1_.x, n1, acc.z); acc.w = fmaf(b1_.y, n1, acc.w);
        acc.x = fmaf(a2.x, n2, acc.x); acc.y = fmaf(a2.y, n2, acc.y);
        acc.z = fmaf(b2_.x, n2, acc.z); acc.w = fmaf(b2_.y, n2, acc.w);
        acc.x = fmaf(a3.x, n3, acc.x); acc.y = fmaf(a3.y, n3, acc.y);
        acc.z = fmaf(b3_.x, n3, acc.z); acc.w = fmaf(b3_.y, n3, acc.w);
    }
    for (; j < end; j++) {
        int s0 = g_csr_src[j];
        float n0 = g_dinv[s0] * did;
        uint2 u0 = ((const uint2*)(h2 + (size_t)s0 * F))[lane];
        float2 a0 = __half22float2(*(const __half2*)&u0.x);
        float2 b0 = __half22float2(*(const __half2*)&u0.y);
        acc.x = fmaf(a0.x, n0, acc.x); acc.y = fmaf(a0.y, n0, acc.y);
        acc.z = fmaf(b0.x, n0, acc.z); acc.w = fmaf(b0.y, n0, acc.w);
    }

    acc.x = acc.x > 0.0f ? acc.x : 0.01f * acc.x;
    acc.y = acc.y > 0.0f ? acc.y : 0.01f * acc.y;
    acc.z = acc.z > 0.0f ? acc.z : 0.01f * acc.z;
    acc.w = acc.w > 0.0f ? acc.w : 0.01f * acc.w;
    ((float4*)(o + (size_t)d * F))[lane] = acc;
}

extern "C" void kernel_launch(void* const* d_in, const int* in_sizes, int n_in,
                              void* d_out, int out_size) {
    // Assign inputs by element count (robust to ordering).
    const float* x = nullptr; const int* ei = nullptr;
    const float* W1 = nullptr; const float* b1 = nullptr;
    const float* W2 = nullptr; const float* b2 = nullptr;
    int x_elems = 0, ei_elems = 0;

    for (int i = 0; i < n_in; i++) {
        int s = in_sizes[i];
        if (s == F * F)      { if (!W1) W1 = (const float*)d_in[i]; else W2 = (const float*)d_in[i]; }
        else if (s == F)     { if (!b1) b1 = (const float*)d_in[i]; else b2 = (const float*)d_in[i]; }
        else if (s > 4 * F * F) {
            if (!x) { x = (const float*)d_in[i]; x_elems = s; }
            else    { ei = (const int*)d_in[i]; ei_elems = s; }
        }
    }
    if (x && ei && x_elems < ei_elems) {
        const float* t = x; x = (const float*)ei; ei = (const int*)t;
        int te = x_elems; x_elems = ei_elems; ei_elems = te;
    }

    const int N = x_elems / F;
    const int E = ei_elems / 2;
    float* out = (float*)d_out;

    float *h, *y; __half *h2;
    cudaGetSymbolAddress((void**)&h,  g_h);
    cudaGetSymbolAddress((void**)&h2, g_h2);
    cudaGetSymbolAddress((void**)&y,  g_y);

    const int TB = 256;
    const int nblk = (N + TB - 1) / TB;
    const int eblk = (E + TB - 1) / TB;
    const int gblk = (N + 31) / 32;
    const int ablk = (N * 32 + TB - 1) / TB;   // warp per node

    // CSR build
    k_detect<<<1, 32>>>(ei, E);
    k_zero<<<nblk, TB>>>(N);
    k_decode_count<<<eblk, TB>>>(ei, E, N);
    k_alloc<<<nblk, TB>>>(N);
    k_place<<<eblk, TB>>>(E, N);

    // ---- layer 1 ----
    k_gemm<<<gblk, 128>>>(x, W1, h, h2, N);
    k_agg<<<ablk, TB>>>(h, h2, b1, y, N);

    // ---- layer 2 ----
    k_gemm<<<gblk, 128>>>(y, W2, h, h2, N);
    k_agg<<<ablk, TB>>>(h, h2, b2, out, N);
}

// round 16
// speedup vs baseline: 1.7608x; 1.6036x over previous
#include <cuda_runtime.h>
#include <cuda_fp16.h>
#include <cstdint>
#include <cstddef>

#define F 128
#define MAXN 100000
#define MAXE 1600000

// Scratch (allocation-free rule: __device__ globals).
__device__ __align__(16) __half g_h2[MAXN * F];   // post-GEMM features (fp16)
__device__ __align__(16) float  g_y[MAXN * F];    // layer-1 activated output
__device__ float g_dinv[MAXN];                    // deg^{-1/2}
__device__ __align__(16) uint4 g_P1[128 * 16 * 4]; // packed split W1 {bh0,bh1,bl0,bl1}
__device__ __align__(16) uint4 g_P2[128 * 16 * 4]; // packed split W2
__device__ int   g_src[MAXE];
__device__ int   g_dst[MAXE];
__device__ int   g_degi[MAXN];
__device__ int   g_beg[MAXN];
__device__ int   g_cursor[MAXN];
__device__ int   g_csr_src[MAXE];
__device__ int   g_is64;
__device__ int   g_total;

static __device__ __forceinline__ uint32_t tf32cvt(float x) {
    uint32_t r; asm("cvt.rna.tf32.f32 %0, %1;" : "=r"(r) : "f"(x)); return r;
}

#define MMA_TF32(c, a0, a1, a2, a3, b0, b1)                                  \
    asm volatile("mma.sync.aligned.m16n8k8.row.col.f32.tf32.tf32.f32 "       \
                 "{%0,%1,%2,%3}, {%4,%5,%6,%7}, {%8,%9}, {%0,%1,%2,%3};"     \
                 : "+f"((c)[0]), "+f"((c)[1]), "+f"((c)[2]), "+f"((c)[3])    \
                 : "r"(a0), "r"(a1), "r"(a2), "r"(a3), "r"(b0), "r"(b1))

// ---------------- edge_index dtype detection ----------------
__global__ void k_detect(const int* __restrict__ w, int E) {
    if (blockIdx.x == 0 && threadIdx.x == 0) {
        int all0 = 1;
        int cnt = E < 256 ? E : 256;
        for (int i = 0; i < cnt; i++)
            if (w[2 * i + 1] != 0) { all0 = 0; break; }
        g_is64 = all0;
    }
}

// ---------------- zero histogram + allocator counter ----------------
__global__ void k_zero(int n) {
    int i = blockIdx.x * blockDim.x + threadIdx.x;
    if (i < n) g_degi[i] = 0;
    if (i == 0) g_total = 0;
}

// ---------------- split W into tf32 hi/lo, packed for LDG.128 --------------
// Entry e = (n*16 + kc)*4 + t  ->  {hi(W[n][kc*8+t]), hi(W[n][kc*8+t+4]),
//                                   lo(..t),          lo(..t+4)}
__global__ void k_wsplit(const float* __restrict__ W1, const float* __restrict__ W2) {
    int i = blockIdx.x * blockDim.x + threadIdx.x;   // 0..16383
    if (i >= 2 * 8192) return;
    const float* W = (i < 8192) ? W1 : W2;
    uint4* P = (i < 8192) ? g_P1 : g_P2;
    int e = i & 8191;
    int nr = e >> 6;
    int kc = (e >> 2) & 15;
    int t  = e & 3;
    int k  = kc * 8 + t;
    float w0 = W[nr * F + k];
    float w1 = W[nr * F + k + 4];
    uint32_t h0 = tf32cvt(w0), h1 = tf32cvt(w1);
    uint32_t l0 = tf32cvt(w0 - __uint_as_float(h0));
    uint32_t l1 = tf32cvt(w1 - __uint_as_float(h1));
    P[e] = make_uint4(h0, h1, l0, l1);
}

// ---------------- decode + degree count in one pass ----------------
__global__ void k_decode_count(const int* __restrict__ w, int E, int n) {
    int e = blockIdx.x * blockDim.x + threadIdx.x;
    if (e < E) {
        int s, d;
        if (g_is64) {
            s = w[2 * e];
            d = w[2 * (E + e)];
        } else {
            s = w[e];
            d = w[E + e];
        }
        g_src[e] = s;
        g_dst[e] = d;
        if ((unsigned)d < (unsigned)n) atomicAdd(&g_degi[d], 1);
    }
}

// ---------------- range allocation + rsqrt ----------------
__global__ void k_alloc(int n) {
    int i = blockIdx.x * blockDim.x + threadIdx.x;
    if (i < n) {
        int deg = g_degi[i];
        int beg = atomicAdd(&g_total, deg);
        g_beg[i] = beg;
        g_cursor[i] = beg;
        g_dinv[i] = rsqrtf((float)deg + 1.0f);
    }
}

// ---------------- edge placement: group src by dst ----------------
__global__ void k_place(int E, int n) {
    int e = blockIdx.x * blockDim.x + threadIdx.x;
    if (e < E) {
        int d = g_dst[e];
        int s = g_src[e];
        if ((unsigned)d < (unsigned)n && (unsigned)s < (unsigned)n) {
            int pos = atomicAdd(&g_cursor[d], 1);
            g_csr_src[pos] = s;
        }
    }
}

// ---------------- GEMM: h2 = fp16(in @ W^T) via tf32 mma + hi/lo split ------
// Block: 128 threads / 4 warps; block tile 64 rows x 128 cols.
// Warp w: rows (w>>1)*32 .. +31 (2 m-tiles), cols (w&1)*64 .. +63 (8 n-tiles).
__global__ void __launch_bounds__(128) k_gemm_mma(const float* __restrict__ in,
                                                  const uint4* __restrict__ P,
                                                  __half* __restrict__ h2,
                                                  int n) {
    __shared__ float xs[64 * 132];   // [row][k], pad 132 -> conflict-free frags
    const int tid = threadIdx.x;
    const int node0 = blockIdx.x * 64;

    for (int idx = tid; idx < 64 * F; idx += 128) {
        int r = idx >> 7, k = idx & 127;
        int nn = node0 + r;
        xs[r * 132 + k] = (nn < n) ? in[(size_t)nn * F + k] : 0.0f;
    }
    __syncthreads();

    const int w = tid >> 5, lane = tid & 31;
    const int g = lane >> 2, t = lane & 3;
    const int r0 = (w >> 1) * 32;         // local row base (2 m-tiles)
    const int nb = (w & 1) * 64;          // col base (8 n-tiles)

    float acc[2][8][4];
#pragma unroll
    for (int mt = 0; mt < 2; mt++)
#pragma unroll
        for (int nt = 0; nt < 8; nt++)
#pragma unroll
            for (int c = 0; c < 4; c++) acc[mt][nt][c] = 0.0f;

#pragma unroll 1
    for (int kc = 0; kc < 16; kc++) {
        const int k0 = kc * 8;
        uint32_t ah[2][4], al[2][4];
#pragma unroll
        for (int mt = 0; mt < 2; mt++) {
            int rb = r0 + mt * 16;
            float a0 = xs[(rb + g) * 132 + k0 + t];
            float a1 = xs[(rb + g + 8) * 132 + k0 + t];
            float a2 = xs[(rb + g) * 132 + k0 + t + 4];
            float a3 = xs[(rb + g + 8) * 132 + k0 + t + 4];
            ah[mt][0] = tf32cvt(a0); al[mt][0] = tf32cvt(a0 - __uint_as_float(ah[mt][0]));
            ah[mt][1] = tf32cvt(a1); al[mt][1] = tf32cvt(a1 - __uint_as_float(ah[mt][1]));
            ah[mt][2] = tf32cvt(a2); al[mt][2] = tf32cvt(a2 - __uint_as_float(ah[mt][2]));
            ah[mt][3] = tf32cvt(a3); al[mt][3] = tf32cvt(a3 - __uint_as_float(ah[mt][3]));
        }
#pragma unroll
        for (int nt = 0; nt < 8; nt++) {
            int nrow = nb + nt * 8 + g;
            uint4 q = P[(nrow * 16 + kc) * 4 + t];   // one LDG.128 = whole frag
#pragma unroll
            for (int mt = 0; mt < 2; mt++) {
                MMA_TF32(acc[mt][nt], ah[mt][0], ah[mt][1], ah[mt][2], ah[mt][3], q.x, q.y);
                MMA_TF32(acc[mt][nt], ah[mt][0], ah[mt][1], ah[mt][2], ah[mt][3], q.z, q.w);
                MMA_TF32(acc[mt][nt], al[mt][0], al[mt][1], al[mt][2], al[mt][3], q.x, q.y);
            }
        }
    }

    // epilogue: fp16 store, c0/c1 at (row g, cols 2t..2t+1), c2/c3 at row g+8
#pragma unroll
    for (int mt = 0; mt < 2; mt++) {
        int row0 = node0 + r0 + mt * 16 + g;
        int row1 = row0 + 8;
#pragma unroll
        for (int nt = 0; nt < 8; nt++) {
            int col = nb + nt * 8 + 2 * t;
            if (row0 < n) {
                __half2 p = __floats2half2_rn(acc[mt][nt][0], acc[mt][nt][1]);
                *(__half2*)&h2[(size_t)row0 * F + col] = p;
            }
            if (row1 < n) {
                __half2 p = __floats2half2_rn(acc[mt][nt][2], acc[mt][nt][3]);
                *(__half2*)&h2[(size_t)row1 * F + col] = p;
            }
        }
    }
}

// ---------------- fused aggregation + self-loop + bias + leaky-relu ---------
// One warp per dst node; lane handles 4 features. All gathers fp16.
__global__ void __launch_bounds__(256) k_agg(const __half* __restrict__ h2,
                                             const float* __restrict__ b,
                                             float* __restrict__ o,
                                             int n) {
    const int lane = threadIdx.x & 31;
    const int d = (blockIdx.x * blockDim.x + threadIdx.x) >> 5;
    if (d >= n) return;

    const int beg = g_beg[d];
    const int end = beg + g_degi[d];
    const float did = g_dinv[d];

    uint2 us = ((const uint2*)(h2 + (size_t)d * F))[lane];
    float2 sa = __half22float2(*(const __half2*)&us.x);
    float2 sb = __half22float2(*(const __half2*)&us.y);
    float4 bb = ((const float4*)b)[lane];
    const float sw = did * did;
    float4 acc;
    acc.x = fmaf(sa.x, sw, bb.x);
    acc.y = fmaf(sa.y, sw, bb.y);
    acc.z = fmaf(sb.x, sw, bb.z);
    acc.w = fmaf(sb.y, sw, bb.w);

    int j = beg;
    for (; j + 7 < end; j += 8) {            // 8-wide for MLP
        int sid[8]; float nw[8]; uint2 u[8];
#pragma unroll
        for (int q = 0; q < 8; q++) sid[q] = g_csr_src[j + q];
#pragma unroll
        for (int q = 0; q < 8; q++) u[q] = ((const uint2*)(h2 + (size_t)sid[q] * F))[lane];
#pragma unroll
        for (int q = 0; q < 8; q++) nw[q] = g_dinv[sid[q]] * did;
#pragma unroll
        for (int q = 0; q < 8; q++) {
            float2 a = __half22float2(*(const __half2*)&u[q].x);
            float2 c = __half22float2(*(const __half2*)&u[q].y);
            acc.x = fmaf(a.x, nw[q], acc.x); acc.y = fmaf(a.y, nw[q], acc.y);
            acc.z = fmaf(c.x, nw[q], acc.z); acc.w = fmaf(c.y, nw[q], acc.w);
        }
    }
    for (; j < end; j++) {
        int s0 = g_csr_src[j];
        float n0 = g_dinv[s0] * did;
        uint2 u0 = ((const uint2*)(h2 + (size_t)s0 * F))[lane];
        float2 a0 = __half22float2(*(const __half2*)&u0.x);
        float2 b0 = __half22float2(*(const __half2*)&u0.y);
        acc.x = fmaf(a0.x, n0, acc.x); acc.y = fmaf(a0.y, n0, acc.y);
        acc.z = fmaf(b0.x, n0, acc.z); acc.w = fmaf(b0.y, n0, acc.w);
    }

    acc.x = acc.x > 0.0f ? acc.x : 0.01f * acc.x;
    acc.y = acc.y > 0.0f ? acc.y : 0.01f * acc.y;
    acc.z = acc.z > 0.0f ? acc.z : 0.01f * acc.z;
    acc.w = acc.w > 0.0f ? acc.w : 0.01f * acc.w;
    ((float4*)(o + (size_t)d * F))[lane] = acc;
}

extern "C" void kernel_launch(void* const* d_in, const int* in_sizes, int n_in,
                              void* d_out, int out_size) {
    // Assign inputs by element count (robust to ordering).
    const float* x = nullptr; const int* ei = nullptr;
    const float* W1 = nullptr; const float* b1 = nullptr;
    const float* W2 = nullptr; const float* b2 = nullptr;
    int x_elems = 0, ei_elems = 0;

    for (int i = 0; i < n_in; i++) {
        int s = in_sizes[i];
        if (s == F * F)      { if (!W1) W1 = (const float*)d_in[i]; else W2 = (const float*)d_in[i]; }
        else if (s == F)     { if (!b1) b1 = (const float*)d_in[i]; else b2 = (const float*)d_in[i]; }
        else if (s > 4 * F * F) {
            if (!x) { x = (const float*)d_in[i]; x_elems = s; }
            else    { ei = (const int*)d_in[i]; ei_elems = s; }
        }
    }
    if (x && ei && x_elems < ei_elems) {
        const float* t = x; x = (const float*)ei; ei = (const int*)t;
        int te = x_elems; x_elems = ei_elems; ei_elems = te;
    }

    const int N = x_elems / F;
    const int E = ei_elems / 2;
    float* out = (float*)d_out;

    __half* h2; float* y; uint4 *P1, *P2;
    cudaGetSymbolAddress((void**)&h2, g_h2);
    cudaGetSymbolAddress((void**)&y,  g_y);
    cudaGetSymbolAddress((void**)&P1, g_P1);
    cudaGetSymbolAddress((void**)&P2, g_P2);

    const int TB = 256;
    const int nblk = (N + TB - 1) / TB;
    const int eblk = (E + TB - 1) / TB;
    const int gblk = (N + 63) / 64;
    const int ablk = (N * 32 + TB - 1) / TB;   // warp per node

    // launch order: ncu window lands on launch #4 = k_gemm_mma (layer 1)
    k_detect<<<1, 32>>>(ei, E);                         // 1
    k_zero<<<nblk, TB>>>(N);                            // 2
    k_wsplit<<<64, 256>>>(W1, W2);                      // 3
    k_gemm_mma<<<gblk, 128>>>(x, P1, h2, N);            // 4  <- profiled
    k_decode_count<<<eblk, TB>>>(ei, E, N);             // 5
    k_alloc<<<nblk, TB>>>(N);                           // 6
    k_place<<<eblk, TB>>>(E, N);                        // 7
    k_agg<<<ablk, TB>>>(h2, b1, y, N);                  // 8

    k_gemm_mma<<<gblk, 128>>>(y, P2, h2, N);            // 9
    k_agg<<<ablk, TB>>>(h2, b2, out, N);                // 10
}